// round 15
// baseline (speedup 1.0000x reference)
#include <cuda_runtime.h>
#include <cuda_bf16.h>
#include <cuda_fp16.h>
#include <stdint.h>
#include <math.h>

#define IN_DIM 64
#define HID    128
#define OUTD   128
#define ETILE  192          // edges per CTA-tile (12 warps x 16)
#define NTHR   384
#define NROWS_N 192
#define MAXN   100000

// ------------------------- scratch (no-alloc rule) --------------------------
__device__ __half g_src_proj[(size_t)MAXN * HID];
__device__ __half g_dst_proj[(size_t)MAXN * HID];

// ------------------------- helpers ------------------------------------------
__device__ __forceinline__ uint32_t smem_u32(const void* p) {
    uint32_t a;
    asm("{ .reg .u64 t; cvta.to.shared.u64 t, %1; cvt.u32.u64 %0, t; }" : "=r"(a) : "l"(p));
    return a;
}
__device__ __forceinline__ void ldsm4(uint32_t* r, uint32_t addr) {
    asm volatile("ldmatrix.sync.aligned.m8n8.x4.shared.b16 {%0,%1,%2,%3}, [%4];"
                 : "=r"(r[0]), "=r"(r[1]), "=r"(r[2]), "=r"(r[3]) : "r"(addr));
}
__device__ __forceinline__ void mma_f16(float* d, const uint32_t* a, uint32_t b0, uint32_t b1) {
    asm volatile("mma.sync.aligned.m16n8k16.row.col.f32.f16.f16.f32 "
                 "{%0,%1,%2,%3}, {%4,%5,%6,%7}, {%8,%9}, {%0,%1,%2,%3};"
                 : "+f"(d[0]), "+f"(d[1]), "+f"(d[2]), "+f"(d[3])
                 : "r"(a[0]), "r"(a[1]), "r"(a[2]), "r"(a[3]), "r"(b0), "r"(b1));
}
__device__ __forceinline__ uint32_t h2pack(float x, float y) {
    uint32_t r;
    asm("cvt.rn.f16x2.f32 %0, %1, %2;" : "=r"(r) : "f"(y), "f"(x));
    return r;
}
__device__ __forceinline__ float2 h2unpack(uint32_t u) {
    __half2 h = *reinterpret_cast<__half2*>(&u);
    return __half22float2(h);
}
__device__ __forceinline__ float fsilu(float x) { return x / (1.0f + __expf(-x)); }

// ------------------------- smem layouts --------------------------------------
#define OFF_F1 0          // 1024 uint4 : [j(16)][s2(2)][lane(32)]
#define OFF_F2 16384      // 2048 uint4 : [j(16)][s2(4)][lane(32)]  (output-permuted rows)
#define OFF_BO 49152
#define OFF_GA 49664
#define OFF_BE 50176
#define SMEM_EDGE_BYTES 50688
// node kernel (fp16 single-pass, output-permuted)
#define W1_STRIDE 72
#define OFF_NSH 0
#define OFF_NDH 18432
#define OFF_NB1 36864
#define SMEM_NODE_BYTES 37376

// ---------------------------------------------------------------------------
// Kernel 1: node projections via fp16 HMMA single-pass, fp16 output.
// Weight rows permuted so thread q owns true output cols 32q..32q+31.
// ---------------------------------------------------------------------------
__global__ __launch_bounds__(NTHR) void node_mma_kernel(
    const float* __restrict__ src_feat, const float* __restrict__ dst_feat,
    const float* __restrict__ W_src, const float* __restrict__ W_dst,
    const float* __restrict__ b1, int Nn, int ntilesN)
{
    extern __shared__ char smraw[];
    char* sm = smraw;
    const uint32_t base = smem_u32(smraw);
    const int tid = threadIdx.x;

    // stage fp16 weights: smem position row n holds W row tau(n)
    {
        __half* sS = (__half*)(sm + OFF_NSH);
        __half* sD = (__half*)(sm + OFF_NDH);
        for (int i = tid; i < HID * (IN_DIM / 2); i += NTHR) {
            int n = i >> 5, p = i & 31;
            int jp = n >> 4, u = (n >> 3) & 1, q2 = (n & 7) >> 1, h = n & 1;
            int tau = 32 * q2 + 4 * jp + 2 * u + h;
            float2 fs = ((const float2*)W_src)[tau * 32 + p];
            float2 fd = ((const float2*)W_dst)[tau * 32 + p];
            *(uint32_t*)(sS + n * W1_STRIDE + 2 * p) = h2pack(fs.x, fs.y);
            *(uint32_t*)(sD + n * W1_STRIDE + 2 * p) = h2pack(fd.x, fd.y);
        }
    }
    if (tid < 128) ((float*)(sm + OFF_NB1))[tid] = b1[tid];
    __syncthreads();

    const int lane = tid & 31, warp = tid >> 5;
    const int qrow = lane >> 2, qcol = lane & 3;
    const int g = lane >> 3, r = lane & 7;
    const int lro = ((g & 2) ? 8 : 0) + r;
    const int lco = (g & 1) * 8;
    const uint32_t lmoff = (uint32_t)(lro * W1_STRIDE + lco) * 2;

    const int nitems = 2 * ntilesN;
    for (int item = blockIdx.x; item < nitems; item += gridDim.x) {
        const bool is_dst = (item >= ntilesN);
        const int tile = is_dst ? (item - ntilesN) : item;
        const float* X = is_dst ? dst_feat : src_feat;
        __half* Out = is_dst ? g_dst_proj : g_src_proj;
        const uint32_t wbase = base + (is_dst ? OFF_NDH : OFF_NSH) + lmoff;

        const int n0w = tile * NROWS_N + warp * 16;
        const int nr0i = n0w + qrow, nr1i = nr0i + 8;
        const int gn0 = (nr0i < Nn) ? nr0i : (Nn - 1);
        const int gn1 = (nr1i < Nn) ? nr1i : (Nn - 1);
        const float* xr0 = X + (size_t)gn0 * IN_DIM + 2 * qcol;
        const float* xr1 = X + (size_t)gn1 * IN_DIM + 2 * qcol;

        uint32_t a[4][4];
        #pragma unroll
        for (int s = 0; s < 4; s++) {
            float2 f0 = *(const float2*)(xr0 + 16 * s);
            float2 f1 = *(const float2*)(xr1 + 16 * s);
            float2 f2 = *(const float2*)(xr0 + 16 * s + 8);
            float2 f3 = *(const float2*)(xr1 + 16 * s + 8);
            a[s][0] = h2pack(f0.x, f0.y);
            a[s][1] = h2pack(f1.x, f1.y);
            a[s][2] = h2pack(f2.x, f2.y);
            a[s][3] = h2pack(f3.x, f3.y);
        }

        float acc[16][4];
        #pragma unroll
        for (int j = 0; j < 16; j++) { acc[j][0]=0.f; acc[j][1]=0.f; acc[j][2]=0.f; acc[j][3]=0.f; }

        #pragma unroll
        for (int s = 0; s < 4; s++) {
            uint32_t bF[8][4];
            #pragma unroll
            for (int jp = 0; jp < 8; jp++)
                ldsm4(bF[jp], wbase + (uint32_t)(jp * 16 * W1_STRIDE + 16 * s) * 2);
            #pragma unroll
            for (int jp = 0; jp < 8; jp++) {
                mma_f16(acc[2*jp],   a[s], bF[jp][0], bF[jp][1]);
                mma_f16(acc[2*jp+1], a[s], bF[jp][2], bF[jp][3]);
            }
        }

        // thread holds true cols 32*qcol + 2j + h  -> contiguous 32-col span
        const float* sb1 = (const float*)(sm + OFF_NB1);
        const bool st0 = (nr0i < Nn), st1 = (nr1i < Nn);
        __half* o0 = Out + (size_t)nr0i * HID + 32 * qcol;
        __half* o1 = Out + (size_t)nr1i * HID + 32 * qcol;
        #pragma unroll
        for (int t = 0; t < 4; t++) {   // cols 8t..8t+7 of the span (j = 4t..4t+3)
            float4 b0v = make_float4(0.f, 0.f, 0.f, 0.f);
            float4 b1v = make_float4(0.f, 0.f, 0.f, 0.f);
            if (is_dst) {
                b0v = *(const float4*)(sb1 + 32 * qcol + 8 * t);
                b1v = *(const float4*)(sb1 + 32 * qcol + 8 * t + 4);
            }
            uint4 p0, p1;
            p0.x = h2pack(acc[4*t+0][0] + b0v.x, acc[4*t+0][1] + b0v.y);
            p0.y = h2pack(acc[4*t+1][0] + b0v.z, acc[4*t+1][1] + b0v.w);
            p0.z = h2pack(acc[4*t+2][0] + b1v.x, acc[4*t+2][1] + b1v.y);
            p0.w = h2pack(acc[4*t+3][0] + b1v.z, acc[4*t+3][1] + b1v.w);
            p1.x = h2pack(acc[4*t+0][2] + b0v.x, acc[4*t+0][3] + b0v.y);
            p1.y = h2pack(acc[4*t+1][2] + b0v.z, acc[4*t+1][3] + b0v.w);
            p1.z = h2pack(acc[4*t+2][2] + b1v.x, acc[4*t+2][3] + b1v.y);
            p1.w = h2pack(acc[4*t+3][2] + b1v.z, acc[4*t+3][3] + b1v.w);
            if (st0) *(uint4*)(o0 + 8 * t) = p0;
            if (st1) *(uint4*)(o1 + 8 * t) = p1;
        }
    }
}

// ---------------------------------------------------------------------------
// Kernel 2: persistent FP16 edge pipeline; fp16 gathers; next-tile idx
// pipelining + L2 prefetch; GEMM2 output-permuted -> contiguous stores.
// ---------------------------------------------------------------------------
__global__ __launch_bounds__(NTHR, 1) void edge_f16_kernel(
    const float* __restrict__ efeat,
    const int* __restrict__ src_idx, const int* __restrict__ dst_idx,
    const float* __restrict__ W_efeat, const float* __restrict__ W_out,
    const float* __restrict__ b_out, const float* __restrict__ gamma,
    const float* __restrict__ beta,
    float* __restrict__ out, int E, int ntiles)
{
    extern __shared__ char smraw[];
    char* sm = smraw;
    const int tid = threadIdx.x;

    // ---- stage W1 frags: [j(16)][s2(2)][lane(32)] (unchanged)
    {
        uint4* f1s = (uint4*)(sm + OFF_F1);
        for (int idx = tid; idx < 1024; idx += NTHR) {
            int j = idx >> 6, rem = idx & 63;
            int s2 = rem >> 5, l = rem & 31;
            int q = l & 3, rho = l >> 2;
            int L = ((rho >> 1) << 5) + 2 * j + (rho & 1);
            const float* wr = W_efeat + L * IN_DIM + q * 16 + s2 * 8;
            float4 wa = *(const float4*)wr;
            float4 wb = *(const float4*)(wr + 4);
            f1s[idx] = make_uint4(h2pack(wa.x, wa.y), h2pack(wa.z, wa.w),
                                  h2pack(wb.x, wb.y), h2pack(wb.z, wb.w));
        }
    }
    // ---- stage W2 frags: [j(16)][s2(4)][lane(32)], row n = output-permuted
    {
        uint4* f2s = (uint4*)(sm + OFF_F2);
        for (int idx = tid; idx < 2048; idx += NTHR) {
            int j = idx >> 7, rem = idx & 127;
            int s2 = rem >> 5, l = rem & 31;
            int q = l & 3, rho = l >> 2;
            int n = 32 * (rho >> 1) + 2 * j + (rho & 1);   // true output col at this position
            const float* wr = W_out + n * HID + q * 32 + s2 * 8;
            float4 wa = *(const float4*)wr;
            float4 wb = *(const float4*)(wr + 4);
            f2s[idx] = make_uint4(h2pack(wa.x, wa.y), h2pack(wa.z, wa.w),
                                  h2pack(wb.x, wb.y), h2pack(wb.z, wb.w));
        }
    }
    if (tid < 128) {
        ((float*)(sm + OFF_BO))[tid] = b_out[tid];
        ((float*)(sm + OFF_GA))[tid] = gamma[tid];
        ((float*)(sm + OFF_BE))[tid] = beta[tid];
    }
    __syncthreads();

    const float* sBO = (const float*)(sm + OFF_BO);
    const float* sGA = (const float*)(sm + OFF_GA);
    const float* sBE = (const float*)(sm + OFF_BE);
    const uint4* f1 = (const uint4*)(sm + OFF_F1);
    const uint4* f2 = (const uint4*)(sm + OFF_F2);

    const int lane = tid & 31, warp = tid >> 5;
    const int qrow = lane >> 2, qcol = lane & 3;

    int tile = blockIdx.x;
    int si0 = 0, di0 = 0, si1 = 0, di1 = 0;
    if (tile < ntiles) {
        const int e0w = tile * ETILE + warp * 16;
        int g0 = e0w + qrow;     if (g0 >= E) g0 = E - 1;
        int g1 = e0w + qrow + 8; if (g1 >= E) g1 = E - 1;
        si0 = src_idx[g0]; di0 = dst_idx[g0];
        si1 = src_idx[g1]; di1 = dst_idx[g1];
    }

    for (; tile < ntiles; ) {
        const int e0w = tile * ETILE + warp * 16;
        const int er0i = e0w + qrow, er1i = er0i + 8;
        const int ge0 = (er0i < E) ? er0i : (E - 1);
        const int ge1 = (er1i < E) ? er1i : (E - 1);

        const uint4* ps0 = (const uint4*)(g_src_proj + (size_t)si0 * HID + qcol * 32);
        const uint4* pd0 = (const uint4*)(g_dst_proj + (size_t)di0 * HID + qcol * 32);
        const uint4* ps1 = (const uint4*)(g_src_proj + (size_t)si1 * HID + qcol * 32);
        const uint4* pd1 = (const uint4*)(g_dst_proj + (size_t)di1 * HID + qcol * 32);

        // ---- A1 fragments (fp16) ----
        uint32_t a1f[4][4];
        {
            const float4* e0p = (const float4*)(efeat + (size_t)ge0 * IN_DIM + qcol * 16);
            const float4* e1p = (const float4*)(efeat + (size_t)ge1 * IN_DIM + qcol * 16);
            #pragma unroll
            for (int s = 0; s < 4; s++) {
                float4 v0 = e0p[s], v1 = e1p[s];
                a1f[s][0] = h2pack(v0.x, v0.y);
                a1f[s][1] = h2pack(v1.x, v1.y);
                a1f[s][2] = h2pack(v0.z, v0.w);
                a1f[s][3] = h2pack(v1.z, v1.w);
            }
        }

        // ---- GEMM1 ----
        float acc1[16][4];
        #pragma unroll
        for (int j = 0; j < 16; j++) { acc1[j][0]=0.f; acc1[j][1]=0.f; acc1[j][2]=0.f; acc1[j][3]=0.f; }
        #pragma unroll
        for (int s2 = 0; s2 < 2; s2++) {
            #pragma unroll
            for (int jg = 0; jg < 4; jg++) {
                const int n0 = 4 * jg;
                uint4 b0 = f1[((n0 + 0) * 2 + s2) * 32 + lane];
                uint4 b1 = f1[((n0 + 1) * 2 + s2) * 32 + lane];
                uint4 b2 = f1[((n0 + 2) * 2 + s2) * 32 + lane];
                uint4 b3 = f1[((n0 + 3) * 2 + s2) * 32 + lane];
                mma_f16(acc1[n0+0], a1f[2*s2],   b0.x, b0.y);
                mma_f16(acc1[n0+1], a1f[2*s2],   b1.x, b1.y);
                mma_f16(acc1[n0+2], a1f[2*s2],   b2.x, b2.y);
                mma_f16(acc1[n0+3], a1f[2*s2],   b3.x, b3.y);
                mma_f16(acc1[n0+0], a1f[2*s2+1], b0.z, b0.w);
                mma_f16(acc1[n0+1], a1f[2*s2+1], b1.z, b1.w);
                mma_f16(acc1[n0+2], a1f[2*s2+1], b2.z, b2.w);
                mma_f16(acc1[n0+3], a1f[2*s2+1], b3.z, b3.w);
            }
        }

        // ---- load NEXT tile's indices ----
        const int ntile = tile + gridDim.x;
        const bool hasnext = (ntile < ntiles);
        int nsi0 = 0, ndi0 = 0, nsi1 = 0, ndi1 = 0, nge0 = 0, nge1 = 0;
        if (hasnext) {
            const int ne0w = ntile * ETILE + warp * 16;
            nge0 = ne0w + qrow;     if (nge0 >= E) nge0 = E - 1;
            nge1 = ne0w + qrow + 8; if (nge1 >= E) nge1 = E - 1;
            nsi0 = src_idx[nge0]; ndi0 = dst_idx[nge0];
            nsi1 = src_idx[nge1]; ndi1 = dst_idx[nge1];
        }

        // ---- gather (fp16) + SiLU + pack GEMM2 A-frags ----
        uint32_t a2f[8][4];
        #pragma unroll
        for (int t = 0; t < 4; t++) {
            uint4 s0v = ps0[t], d0v = pd0[t];
            uint4 s1v = ps1[t], d1v = pd1[t];
            {
                const int s = 2 * t;
                float2 gs0a = h2unpack(s0v.x), gs0b = h2unpack(s0v.y);
                float2 gd0a = h2unpack(d0v.x), gd0b = h2unpack(d0v.y);
                float2 gs1a = h2unpack(s1v.x), gs1b = h2unpack(s1v.y);
                float2 gd1a = h2unpack(d1v.x), gd1b = h2unpack(d1v.y);
                float u0 = fsilu(acc1[2*s][0]   + gs0a.x + gd0a.x);
                float u1 = fsilu(acc1[2*s][1]   + gs0a.y + gd0a.y);
                float u2 = fsilu(acc1[2*s+1][0] + gs0b.x + gd0b.x);
                float u3 = fsilu(acc1[2*s+1][1] + gs0b.y + gd0b.y);
                float w0 = fsilu(acc1[2*s][2]   + gs1a.x + gd1a.x);
                float w1 = fsilu(acc1[2*s][3]   + gs1a.y + gd1a.y);
                float w2 = fsilu(acc1[2*s+1][2] + gs1b.x + gd1b.x);
                float w3 = fsilu(acc1[2*s+1][3] + gs1b.y + gd1b.y);
                a2f[s][0] = h2pack(u0, u1);
                a2f[s][1] = h2pack(w0, w1);
                a2f[s][2] = h2pack(u2, u3);
                a2f[s][3] = h2pack(w2, w3);
            }
            {
                const int s = 2 * t + 1;
                float2 gs0a = h2unpack(s0v.z), gs0b = h2unpack(s0v.w);
                float2 gd0a = h2unpack(d0v.z), gd0b = h2unpack(d0v.w);
                float2 gs1a = h2unpack(s1v.z), gs1b = h2unpack(s1v.w);
                float2 gd1a = h2unpack(d1v.z), gd1b = h2unpack(d1v.w);
                float u0 = fsilu(acc1[2*s][0]   + gs0a.x + gd0a.x);
                float u1 = fsilu(acc1[2*s][1]   + gs0a.y + gd0a.y);
                float u2 = fsilu(acc1[2*s+1][0] + gs0b.x + gd0b.x);
                float u3 = fsilu(acc1[2*s+1][1] + gs0b.y + gd0b.y);
                float w0 = fsilu(acc1[2*s][2]   + gs1a.x + gd1a.x);
                float w1 = fsilu(acc1[2*s][3]   + gs1a.y + gd1a.y);
                float w2 = fsilu(acc1[2*s+1][2] + gs1b.x + gd1b.x);
                float w3 = fsilu(acc1[2*s+1][3] + gs1b.y + gd1b.y);
                a2f[s][0] = h2pack(u0, u1);
                a2f[s][1] = h2pack(w0, w1);
                a2f[s][2] = h2pack(u2, u3);
                a2f[s][3] = h2pack(w2, w3);
            }
        }

        // ---- prefetch NEXT tile's gather rows + efeat rows into L2 ----
        if (hasnext) {
            asm volatile("prefetch.global.L2 [%0];" :: "l"(g_src_proj + (size_t)nsi0 * HID + qcol * 32));
            asm volatile("prefetch.global.L2 [%0];" :: "l"(g_dst_proj + (size_t)ndi0 * HID + qcol * 32));
            asm volatile("prefetch.global.L2 [%0];" :: "l"(g_src_proj + (size_t)nsi1 * HID + qcol * 32));
            asm volatile("prefetch.global.L2 [%0];" :: "l"(g_dst_proj + (size_t)ndi1 * HID + qcol * 32));
            asm volatile("prefetch.global.L2 [%0];" :: "l"(efeat + (size_t)nge0 * IN_DIM + qcol * 16));
            asm volatile("prefetch.global.L2 [%0];" :: "l"(efeat + (size_t)nge1 * IN_DIM + qcol * 16));
        }

        // ---- GEMM2 (output-permuted W2) ----
        float acc2[16][4];
        #pragma unroll
        for (int j = 0; j < 16; j++) { acc2[j][0]=0.f; acc2[j][1]=0.f; acc2[j][2]=0.f; acc2[j][3]=0.f; }
        #pragma unroll
        for (int s2 = 0; s2 < 4; s2++) {
            #pragma unroll
            for (int jg = 0; jg < 4; jg++) {
                const int n0 = 4 * jg;
                uint4 b0 = f2[((n0 + 0) * 4 + s2) * 32 + lane];
                uint4 b1 = f2[((n0 + 1) * 4 + s2) * 32 + lane];
                uint4 b2 = f2[((n0 + 2) * 4 + s2) * 32 + lane];
                uint4 b3 = f2[((n0 + 3) * 4 + s2) * 32 + lane];
                mma_f16(acc2[n0+0], a2f[2*s2],   b0.x, b0.y);
                mma_f16(acc2[n0+1], a2f[2*s2],   b1.x, b1.y);
                mma_f16(acc2[n0+2], a2f[2*s2],   b2.x, b2.y);
                mma_f16(acc2[n0+3], a2f[2*s2],   b3.x, b3.y);
                mma_f16(acc2[n0+0], a2f[2*s2+1], b0.z, b0.w);
                mma_f16(acc2[n0+1], a2f[2*s2+1], b1.z, b1.w);
                mma_f16(acc2[n0+2], a2f[2*s2+1], b2.z, b2.w);
                mma_f16(acc2[n0+3], a2f[2*s2+1], b3.z, b3.w);
            }
        }

        // ---- bias + LayerNorm + contiguous float4 stores ----
        // thread holds true cols 32*qcol + 2j + h
        float s0 = 0.f, ss0 = 0.f, s1 = 0.f, ss1 = 0.f;
        #pragma unroll
        for (int j = 0; j < 16; j++) {
            float2 bo = *(const float2*)(sBO + 32 * qcol + 2 * j);
            acc2[j][0] += bo.x; acc2[j][1] += bo.y;
            acc2[j][2] += bo.x; acc2[j][3] += bo.y;
            s0  += acc2[j][0] + acc2[j][1];
            ss0 += acc2[j][0] * acc2[j][0] + acc2[j][1] * acc2[j][1];
            s1  += acc2[j][2] + acc2[j][3];
            ss1 += acc2[j][2] * acc2[j][2] + acc2[j][3] * acc2[j][3];
        }
        s0  += __shfl_xor_sync(0xffffffffu, s0, 1);  s0  += __shfl_xor_sync(0xffffffffu, s0, 2);
        ss0 += __shfl_xor_sync(0xffffffffu, ss0, 1); ss0 += __shfl_xor_sync(0xffffffffu, ss0, 2);
        s1  += __shfl_xor_sync(0xffffffffu, s1, 1);  s1  += __shfl_xor_sync(0xffffffffu, s1, 2);
        ss1 += __shfl_xor_sync(0xffffffffu, ss1, 1); ss1 += __shfl_xor_sync(0xffffffffu, ss1, 2);

        const float m0 = s0 * (1.0f / OUTD);
        const float v0 = ss0 * (1.0f / OUTD) - m0 * m0;
        const float i0 = rsqrtf(v0 + 1e-5f);
        const float m1 = s1 * (1.0f / OUTD);
        const float v1 = ss1 * (1.0f / OUTD) - m1 * m1;
        const float i1 = rsqrtf(v1 + 1e-5f);

        const bool st0 = (er0i < E), st1 = (er1i < E);
        float* o0 = out + (size_t)er0i * OUTD + 32 * qcol;
        float* o1 = out + (size_t)er1i * OUTD + 32 * qcol;
        #pragma unroll
        for (int t = 0; t < 8; t++) {   // cols 4t..4t+3 of span (j = 2t, 2t+1)
            float4 ga = *(const float4*)(sGA + 32 * qcol + 4 * t);
            float4 be = *(const float4*)(sBE + 32 * qcol + 4 * t);
            if (st0) {
                float4 w;
                w.x = (acc2[2*t][0]   - m0) * i0 * ga.x + be.x;
                w.y = (acc2[2*t][1]   - m0) * i0 * ga.y + be.y;
                w.z = (acc2[2*t+1][0] - m0) * i0 * ga.z + be.z;
                w.w = (acc2[2*t+1][1] - m0) * i0 * ga.w + be.w;
                *(float4*)(o0 + 4 * t) = w;
            }
            if (st1) {
                float4 w;
                w.x = (acc2[2*t][2]   - m1) * i1 * ga.x + be.x;
                w.y = (acc2[2*t][3]   - m1) * i1 * ga.y + be.y;
                w.z = (acc2[2*t+1][2] - m1) * i1 * ga.z + be.z;
                w.w = (acc2[2*t+1][3] - m1) * i1 * ga.w + be.w;
                *(float4*)(o1 + 4 * t) = w;
            }
        }

        tile = ntile;
        si0 = nsi0; di0 = ndi0; si1 = nsi1; di1 = ndi1;
    }
}

// ---------------------------------------------------------------------------
extern "C" void kernel_launch(void* const* d_in, const int* in_sizes, int n_in,
                              void* d_out, int out_size)
{
    const float* efeat    = (const float*)d_in[0];
    const float* src_feat = (const float*)d_in[1];
    const float* dst_feat = (const float*)d_in[2];
    const int*   src_idx  = (const int*)d_in[3];
    const int*   dst_idx  = (const int*)d_in[4];
    const float* W_efeat  = (const float*)d_in[5];
    const float* W_src    = (const float*)d_in[6];
    const float* W_dst    = (const float*)d_in[7];
    const float* b1       = (const float*)d_in[8];
    const float* W_out    = (const float*)d_in[9];
    const float* b_out    = (const float*)d_in[10];
    const float* ln_gamma = (const float*)d_in[11];
    const float* ln_beta  = (const float*)d_in[12];
    float* out = (float*)d_out;

    const int E  = in_sizes[0] / IN_DIM;
    const int Nn = in_sizes[1] / IN_DIM;
    const int ntiles  = (E + ETILE - 1) / ETILE;
    const int ntilesN = (Nn + NROWS_N - 1) / NROWS_N;

    cudaFuncSetAttribute(node_mma_kernel, cudaFuncAttributeMaxDynamicSharedMemorySize, SMEM_NODE_BYTES);
    cudaFuncSetAttribute(edge_f16_kernel, cudaFuncAttributeMaxDynamicSharedMemorySize, SMEM_EDGE_BYTES);

    int nsm = 148;
    cudaDeviceGetAttribute(&nsm, cudaDevAttrMultiProcessorCount, 0);

    int gridN = 2 * ntilesN < nsm ? 2 * ntilesN : nsm;
    node_mma_kernel<<<gridN, NTHR, SMEM_NODE_BYTES>>>(src_feat, dst_feat, W_src, W_dst, b1, Nn, ntilesN);

    int grid = (ntiles < nsm) ? ntiles : nsm;
    edge_f16_kernel<<<grid, NTHR, SMEM_EDGE_BYTES>>>(efeat, src_idx, dst_idx, W_efeat, W_out,
                                                     b_out, ln_gamma, ln_beta, out, E, ntiles);
}

// round 16
// speedup vs baseline: 1.2456x; 1.2456x over previous
#include <cuda_runtime.h>
#include <cuda_bf16.h>
#include <cuda_fp16.h>
#include <stdint.h>
#include <math.h>

#define IN_DIM 64
#define HID    128
#define OUTD   128
#define ETILE  192          // edges per CTA-tile (12 warps x 16)
#define NTHR   384
#define NROWS_N 192
#define MAXN   100000

// ------------------------- scratch (no-alloc rule) --------------------------
__device__ __half g_src_proj[(size_t)MAXN * HID];
__device__ __half g_dst_proj[(size_t)MAXN * HID];

// ------------------------- helpers ------------------------------------------
__device__ __forceinline__ uint32_t smem_u32(const void* p) {
    uint32_t a;
    asm("{ .reg .u64 t; cvta.to.shared.u64 t, %1; cvt.u32.u64 %0, t; }" : "=r"(a) : "l"(p));
    return a;
}
__device__ __forceinline__ void ldsm4(uint32_t* r, uint32_t addr) {
    asm volatile("ldmatrix.sync.aligned.m8n8.x4.shared.b16 {%0,%1,%2,%3}, [%4];"
                 : "=r"(r[0]), "=r"(r[1]), "=r"(r[2]), "=r"(r[3]) : "r"(addr));
}
__device__ __forceinline__ void mma_f16(float* d, const uint32_t* a, uint32_t b0, uint32_t b1) {
    asm volatile("mma.sync.aligned.m16n8k16.row.col.f32.f16.f16.f32 "
                 "{%0,%1,%2,%3}, {%4,%5,%6,%7}, {%8,%9}, {%0,%1,%2,%3};"
                 : "+f"(d[0]), "+f"(d[1]), "+f"(d[2]), "+f"(d[3])
                 : "r"(a[0]), "r"(a[1]), "r"(a[2]), "r"(a[3]), "r"(b0), "r"(b1));
}
__device__ __forceinline__ uint32_t h2pack(float x, float y) {
    uint32_t r;
    asm("cvt.rn.f16x2.f32 %0, %1, %2;" : "=r"(r) : "f"(y), "f"(x));
    return r;
}
__device__ __forceinline__ float2 h2unpack(uint32_t u) {
    __half2 h = *reinterpret_cast<__half2*>(&u);
    return __half22float2(h);
}
__device__ __forceinline__ float fsilu(float x) { return x / (1.0f + __expf(-x)); }

// ------------------------- smem layouts --------------------------------------
#define OFF_F1 0          // 1024 uint4 : [j(16)][s2(2)][lane(32)]
#define OFF_F2 16384      // 2048 uint4 : [j(16)][s2(4)][lane(32)]  (store-permuted rows)
#define OFF_BO 49152
#define OFF_GA 49664
#define OFF_BE 50176
#define SMEM_EDGE_BYTES 50688
// node kernel (fp16 single-pass) — exactly R14
#define W1_STRIDE 72
#define OFF_NSH 0
#define OFF_NDH 18432
#define OFF_NB1 36864
#define SMEM_NODE_BYTES 37376

// ---------------------------------------------------------------------------
// Kernel 1: node projections via fp16 HMMA single-pass, fp16 output (R14)
// ---------------------------------------------------------------------------
__global__ __launch_bounds__(NTHR) void node_mma_kernel(
    const float* __restrict__ src_feat, const float* __restrict__ dst_feat,
    const float* __restrict__ W_src, const float* __restrict__ W_dst,
    const float* __restrict__ b1, int Nn, int ntilesN)
{
    extern __shared__ char smraw[];
    char* sm = smraw;
    const uint32_t base = smem_u32(smraw);
    const int tid = threadIdx.x;

    {
        __half* sS = (__half*)(sm + OFF_NSH);
        __half* sD = (__half*)(sm + OFF_NDH);
        for (int i = tid; i < HID * (IN_DIM / 2); i += NTHR) {
            int n = i >> 5, p = i & 31;
            float2 fs = ((const float2*)W_src)[n * 32 + p];
            float2 fd = ((const float2*)W_dst)[n * 32 + p];
            *(uint32_t*)(sS + n * W1_STRIDE + 2 * p) = h2pack(fs.x, fs.y);
            *(uint32_t*)(sD + n * W1_STRIDE + 2 * p) = h2pack(fd.x, fd.y);
        }
    }
    if (tid < 128) ((float*)(sm + OFF_NB1))[tid] = b1[tid];
    __syncthreads();

    const int lane = tid & 31, warp = tid >> 5;
    const int qrow = lane >> 2, qcol = lane & 3;
    const int g = lane >> 3, r = lane & 7;
    const int lro = ((g & 2) ? 8 : 0) + r;
    const int lco = (g & 1) * 8;
    const uint32_t lmoff = (uint32_t)(lro * W1_STRIDE + lco) * 2;

    const int nitems = 2 * ntilesN;
    for (int item = blockIdx.x; item < nitems; item += gridDim.x) {
        const bool is_dst = (item >= ntilesN);
        const int tile = is_dst ? (item - ntilesN) : item;
        const float* X = is_dst ? dst_feat : src_feat;
        __half* Out = is_dst ? g_dst_proj : g_src_proj;
        const uint32_t wbase = base + (is_dst ? OFF_NDH : OFF_NSH) + lmoff;

        const int n0w = tile * NROWS_N + warp * 16;
        const int nr0i = n0w + qrow, nr1i = nr0i + 8;
        const int gn0 = (nr0i < Nn) ? nr0i : (Nn - 1);
        const int gn1 = (nr1i < Nn) ? nr1i : (Nn - 1);
        const float* xr0 = X + (size_t)gn0 * IN_DIM + 2 * qcol;
        const float* xr1 = X + (size_t)gn1 * IN_DIM + 2 * qcol;

        uint32_t a[4][4];
        #pragma unroll
        for (int s = 0; s < 4; s++) {
            float2 f0 = *(const float2*)(xr0 + 16 * s);
            float2 f1 = *(const float2*)(xr1 + 16 * s);
            float2 f2 = *(const float2*)(xr0 + 16 * s + 8);
            float2 f3 = *(const float2*)(xr1 + 16 * s + 8);
            a[s][0] = h2pack(f0.x, f0.y);
            a[s][1] = h2pack(f1.x, f1.y);
            a[s][2] = h2pack(f2.x, f2.y);
            a[s][3] = h2pack(f3.x, f3.y);
        }

        float acc[16][4];
        #pragma unroll
        for (int j = 0; j < 16; j++) { acc[j][0]=0.f; acc[j][1]=0.f; acc[j][2]=0.f; acc[j][3]=0.f; }

        #pragma unroll
        for (int s = 0; s < 4; s++) {
            uint32_t bF[8][4];
            #pragma unroll
            for (int jp = 0; jp < 8; jp++)
                ldsm4(bF[jp], wbase + (uint32_t)(jp * 16 * W1_STRIDE + 16 * s) * 2);
            #pragma unroll
            for (int jp = 0; jp < 8; jp++) {
                mma_f16(acc[2*jp],   a[s], bF[jp][0], bF[jp][1]);
                mma_f16(acc[2*jp+1], a[s], bF[jp][2], bF[jp][3]);
            }
        }

        const float* sb1 = (const float*)(sm + OFF_NB1);
        const bool st0 = (nr0i < Nn), st1 = (nr1i < Nn);
        __half* o0 = Out + (size_t)nr0i * HID + 2 * qcol;
        __half* o1 = Out + (size_t)nr1i * HID + 2 * qcol;
        #pragma unroll
        for (int j = 0; j < 16; j++) {
            float2 bb = make_float2(0.f, 0.f);
            if (is_dst) bb = *(const float2*)(sb1 + 8 * j + 2 * qcol);
            if (st0) *(uint32_t*)(o0 + 8 * j) = h2pack(acc[j][0] + bb.x, acc[j][1] + bb.y);
            if (st1) *(uint32_t*)(o1 + 8 * j) = h2pack(acc[j][2] + bb.x, acc[j][3] + bb.y);
        }
    }
}

// ---------------------------------------------------------------------------
// Kernel 2: persistent FP16 edge pipeline (R14) + lane-coalesced store perm:
//   fragment position p = 8j + 2q + h  <->  true col 16*(j>>1) + 4q + 2*(j&1) + h
// ---------------------------------------------------------------------------
__global__ __launch_bounds__(NTHR, 1) void edge_f16_kernel(
    const float* __restrict__ efeat,
    const int* __restrict__ src_idx, const int* __restrict__ dst_idx,
    const float* __restrict__ W_efeat, const float* __restrict__ W_out,
    const float* __restrict__ b_out, const float* __restrict__ gamma,
    const float* __restrict__ beta,
    float* __restrict__ out, int E, int ntiles)
{
    extern __shared__ char smraw[];
    char* sm = smraw;
    const int tid = threadIdx.x;

    // ---- stage W1 frags: [j(16)][s2(2)][lane(32)] (unchanged)
    {
        uint4* f1s = (uint4*)(sm + OFF_F1);
        for (int idx = tid; idx < 1024; idx += NTHR) {
            int j = idx >> 6, rem = idx & 63;
            int s2 = rem >> 5, l = rem & 31;
            int q = l & 3, rho = l >> 2;
            int L = ((rho >> 1) << 5) + 2 * j + (rho & 1);
            const float* wr = W_efeat + L * IN_DIM + q * 16 + s2 * 8;
            float4 wa = *(const float4*)wr;
            float4 wb = *(const float4*)(wr + 4);
            f1s[idx] = make_uint4(h2pack(wa.x, wa.y), h2pack(wa.z, wa.w),
                                  h2pack(wb.x, wb.y), h2pack(wb.z, wb.w));
        }
    }
    // ---- stage W2 frags: [j(16)][s2(4)][lane(32)], store-permuted rows:
    //      position (j, rho) holds W_out row 16*(j>>1) + 4*(rho>>1) + 2*(j&1) + (rho&1)
    {
        uint4* f2s = (uint4*)(sm + OFF_F2);
        for (int idx = tid; idx < 2048; idx += NTHR) {
            int j = idx >> 7, rem = idx & 127;
            int s2 = rem >> 5, l = rem & 31;
            int q = l & 3, rho = l >> 2;
            int n = 16 * (j >> 1) + 4 * (rho >> 1) + 2 * (j & 1) + (rho & 1);
            const float* wr = W_out + n * HID + q * 32 + s2 * 8;
            float4 wa = *(const float4*)wr;
            float4 wb = *(const float4*)(wr + 4);
            f2s[idx] = make_uint4(h2pack(wa.x, wa.y), h2pack(wa.z, wa.w),
                                  h2pack(wb.x, wb.y), h2pack(wb.z, wb.w));
        }
    }
    if (tid < 128) {
        ((float*)(sm + OFF_BO))[tid] = b_out[tid];
        ((float*)(sm + OFF_GA))[tid] = gamma[tid];
        ((float*)(sm + OFF_BE))[tid] = beta[tid];
    }
    __syncthreads();

    const float* sBO = (const float*)(sm + OFF_BO);
    const float* sGA = (const float*)(sm + OFF_GA);
    const float* sBE = (const float*)(sm + OFF_BE);
    const uint4* f1 = (const uint4*)(sm + OFF_F1);
    const uint4* f2 = (const uint4*)(sm + OFF_F2);

    const int lane = tid & 31, warp = tid >> 5;
    const int qrow = lane >> 2, qcol = lane & 3;

    int tile = blockIdx.x;
    int si0 = 0, di0 = 0, si1 = 0, di1 = 0;
    if (tile < ntiles) {
        const int e0w = tile * ETILE + warp * 16;
        int g0 = e0w + qrow;     if (g0 >= E) g0 = E - 1;
        int g1 = e0w + qrow + 8; if (g1 >= E) g1 = E - 1;
        si0 = src_idx[g0]; di0 = dst_idx[g0];
        si1 = src_idx[g1]; di1 = dst_idx[g1];
    }

    for (; tile < ntiles; ) {
        const int e0w = tile * ETILE + warp * 16;
        const int er0i = e0w + qrow, er1i = er0i + 8;
        const int ge0 = (er0i < E) ? er0i : (E - 1);
        const int ge1 = (er1i < E) ? er1i : (E - 1);

        const uint4* ps0 = (const uint4*)(g_src_proj + (size_t)si0 * HID + qcol * 32);
        const uint4* pd0 = (const uint4*)(g_dst_proj + (size_t)di0 * HID + qcol * 32);
        const uint4* ps1 = (const uint4*)(g_src_proj + (size_t)si1 * HID + qcol * 32);
        const uint4* pd1 = (const uint4*)(g_dst_proj + (size_t)di1 * HID + qcol * 32);

        // ---- A1 fragments (fp16) ----
        uint32_t a1f[4][4];
        {
            const float4* e0p = (const float4*)(efeat + (size_t)ge0 * IN_DIM + qcol * 16);
            const float4* e1p = (const float4*)(efeat + (size_t)ge1 * IN_DIM + qcol * 16);
            #pragma unroll
            for (int s = 0; s < 4; s++) {
                float4 v0 = e0p[s], v1 = e1p[s];
                a1f[s][0] = h2pack(v0.x, v0.y);
                a1f[s][1] = h2pack(v1.x, v1.y);
                a1f[s][2] = h2pack(v0.z, v0.w);
                a1f[s][3] = h2pack(v1.z, v1.w);
            }
        }

        // ---- GEMM1 ----
        float acc1[16][4];
        #pragma unroll
        for (int j = 0; j < 16; j++) { acc1[j][0]=0.f; acc1[j][1]=0.f; acc1[j][2]=0.f; acc1[j][3]=0.f; }
        #pragma unroll
        for (int s2 = 0; s2 < 2; s2++) {
            #pragma unroll
            for (int jg = 0; jg < 4; jg++) {
                const int n0 = 4 * jg;
                uint4 b0 = f1[((n0 + 0) * 2 + s2) * 32 + lane];
                uint4 b1 = f1[((n0 + 1) * 2 + s2) * 32 + lane];
                uint4 b2 = f1[((n0 + 2) * 2 + s2) * 32 + lane];
                uint4 b3 = f1[((n0 + 3) * 2 + s2) * 32 + lane];
                mma_f16(acc1[n0+0], a1f[2*s2],   b0.x, b0.y);
                mma_f16(acc1[n0+1], a1f[2*s2],   b1.x, b1.y);
                mma_f16(acc1[n0+2], a1f[2*s2],   b2.x, b2.y);
                mma_f16(acc1[n0+3], a1f[2*s2],   b3.x, b3.y);
                mma_f16(acc1[n0+0], a1f[2*s2+1], b0.z, b0.w);
                mma_f16(acc1[n0+1], a1f[2*s2+1], b1.z, b1.w);
                mma_f16(acc1[n0+2], a1f[2*s2+1], b2.z, b2.w);
                mma_f16(acc1[n0+3], a1f[2*s2+1], b3.z, b3.w);
            }
        }

        // ---- load NEXT tile's indices ----
        const int ntile = tile + gridDim.x;
        const bool hasnext = (ntile < ntiles);
        int nsi0 = 0, ndi0 = 0, nsi1 = 0, ndi1 = 0, nge0 = 0, nge1 = 0;
        if (hasnext) {
            const int ne0w = ntile * ETILE + warp * 16;
            nge0 = ne0w + qrow;     if (nge0 >= E) nge0 = E - 1;
            nge1 = ne0w + qrow + 8; if (nge1 >= E) nge1 = E - 1;
            nsi0 = src_idx[nge0]; ndi0 = dst_idx[nge0];
            nsi1 = src_idx[nge1]; ndi1 = dst_idx[nge1];
        }

        // ---- gather (fp16) + SiLU + pack GEMM2 A-frags ----
        uint32_t a2f[8][4];
        #pragma unroll
        for (int t = 0; t < 4; t++) {
            uint4 s0v = ps0[t], d0v = pd0[t];
            uint4 s1v = ps1[t], d1v = pd1[t];
            {
                const int s = 2 * t;
                float2 gs0a = h2unpack(s0v.x), gs0b = h2unpack(s0v.y);
                float2 gd0a = h2unpack(d0v.x), gd0b = h2unpack(d0v.y);
                float2 gs1a = h2unpack(s1v.x), gs1b = h2unpack(s1v.y);
                float2 gd1a = h2unpack(d1v.x), gd1b = h2unpack(d1v.y);
                float u0 = fsilu(acc1[2*s][0]   + gs0a.x + gd0a.x);
                float u1 = fsilu(acc1[2*s][1]   + gs0a.y + gd0a.y);
                float u2 = fsilu(acc1[2*s+1][0] + gs0b.x + gd0b.x);
                float u3 = fsilu(acc1[2*s+1][1] + gs0b.y + gd0b.y);
                float w0 = fsilu(acc1[2*s][2]   + gs1a.x + gd1a.x);
                float w1 = fsilu(acc1[2*s][3]   + gs1a.y + gd1a.y);
                float w2 = fsilu(acc1[2*s+1][2] + gs1b.x + gd1b.x);
                float w3 = fsilu(acc1[2*s+1][3] + gs1b.y + gd1b.y);
                a2f[s][0] = h2pack(u0, u1);
                a2f[s][1] = h2pack(w0, w1);
                a2f[s][2] = h2pack(u2, u3);
                a2f[s][3] = h2pack(w2, w3);
            }
            {
                const int s = 2 * t + 1;
                float2 gs0a = h2unpack(s0v.z), gs0b = h2unpack(s0v.w);
                float2 gd0a = h2unpack(d0v.z), gd0b = h2unpack(d0v.w);
                float2 gs1a = h2unpack(s1v.z), gs1b = h2unpack(s1v.w);
                float2 gd1a = h2unpack(d1v.z), gd1b = h2unpack(d1v.w);
                float u0 = fsilu(acc1[2*s][0]   + gs0a.x + gd0a.x);
                float u1 = fsilu(acc1[2*s][1]   + gs0a.y + gd0a.y);
                float u2 = fsilu(acc1[2*s+1][0] + gs0b.x + gd0b.x);
                float u3 = fsilu(acc1[2*s+1][1] + gs0b.y + gd0b.y);
                float w0 = fsilu(acc1[2*s][2]   + gs1a.x + gd1a.x);
                float w1 = fsilu(acc1[2*s][3]   + gs1a.y + gd1a.y);
                float w2 = fsilu(acc1[2*s+1][2] + gs1b.x + gd1b.x);
                float w3 = fsilu(acc1[2*s+1][3] + gs1b.y + gd1b.y);
                a2f[s][0] = h2pack(u0, u1);
                a2f[s][1] = h2pack(w0, w1);
                a2f[s][2] = h2pack(u2, u3);
                a2f[s][3] = h2pack(w2, w3);
            }
        }

        // ---- prefetch NEXT tile's gather rows + efeat rows into L2 ----
        if (hasnext) {
            asm volatile("prefetch.global.L2 [%0];" :: "l"(g_src_proj + (size_t)nsi0 * HID + qcol * 32));
            asm volatile("prefetch.global.L2 [%0];" :: "l"(g_dst_proj + (size_t)ndi0 * HID + qcol * 32));
            asm volatile("prefetch.global.L2 [%0];" :: "l"(g_src_proj + (size_t)nsi1 * HID + qcol * 32));
            asm volatile("prefetch.global.L2 [%0];" :: "l"(g_dst_proj + (size_t)ndi1 * HID + qcol * 32));
            asm volatile("prefetch.global.L2 [%0];" :: "l"(efeat + (size_t)nge0 * IN_DIM + qcol * 16));
            asm volatile("prefetch.global.L2 [%0];" :: "l"(efeat + (size_t)nge1 * IN_DIM + qcol * 16));
        }

        // ---- GEMM2 (store-permuted W2) ----
        float acc2[16][4];
        #pragma unroll
        for (int j = 0; j < 16; j++) { acc2[j][0]=0.f; acc2[j][1]=0.f; acc2[j][2]=0.f; acc2[j][3]=0.f; }
        #pragma unroll
        for (int s2 = 0; s2 < 4; s2++) {
            #pragma unroll
            for (int jg = 0; jg < 4; jg++) {
                const int n0 = 4 * jg;
                uint4 b0 = f2[((n0 + 0) * 4 + s2) * 32 + lane];
                uint4 b1 = f2[((n0 + 1) * 4 + s2) * 32 + lane];
                uint4 b2 = f2[((n0 + 2) * 4 + s2) * 32 + lane];
                uint4 b3 = f2[((n0 + 3) * 4 + s2) * 32 + lane];
                mma_f16(acc2[n0+0], a2f[2*s2],   b0.x, b0.y);
                mma_f16(acc2[n0+1], a2f[2*s2],   b1.x, b1.y);
                mma_f16(acc2[n0+2], a2f[2*s2],   b2.x, b2.y);
                mma_f16(acc2[n0+3], a2f[2*s2],   b3.x, b3.y);
                mma_f16(acc2[n0+0], a2f[2*s2+1], b0.z, b0.w);
                mma_f16(acc2[n0+1], a2f[2*s2+1], b1.z, b1.w);
                mma_f16(acc2[n0+2], a2f[2*s2+1], b2.z, b2.w);
                mma_f16(acc2[n0+3], a2f[2*s2+1], b3.z, b3.w);
            }
        }

        // ---- bias + LayerNorm + 64B-coalesced float4 stores ----
        // thread (j,h) holds true col 16*(j>>1) + 4*qcol + 2*(j&1) + h
        float s0 = 0.f, ss0 = 0.f, s1 = 0.f, ss1 = 0.f;
        #pragma unroll
        for (int j = 0; j < 16; j++) {
            float2 bo = *(const float2*)(sBO + 16 * (j >> 1) + 4 * qcol + 2 * (j & 1));
            acc2[j][0] += bo.x; acc2[j][1] += bo.y;
            acc2[j][2] += bo.x; acc2[j][3] += bo.y;
            s0  += acc2[j][0] + acc2[j][1];
            ss0 += acc2[j][0] * acc2[j][0] + acc2[j][1] * acc2[j][1];
            s1  += acc2[j][2] + acc2[j][3];
            ss1 += acc2[j][2] * acc2[j][2] + acc2[j][3] * acc2[j][3];
        }
        s0  += __shfl_xor_sync(0xffffffffu, s0, 1);  s0  += __shfl_xor_sync(0xffffffffu, s0, 2);
        ss0 += __shfl_xor_sync(0xffffffffu, ss0, 1); ss0 += __shfl_xor_sync(0xffffffffu, ss0, 2);
        s1  += __shfl_xor_sync(0xffffffffu, s1, 1);  s1  += __shfl_xor_sync(0xffffffffu, s1, 2);
        ss1 += __shfl_xor_sync(0xffffffffu, ss1, 1); ss1 += __shfl_xor_sync(0xffffffffu, ss1, 2);

        const float m0 = s0 * (1.0f / OUTD);
        const float v0 = ss0 * (1.0f / OUTD) - m0 * m0;
        const float i0 = rsqrtf(v0 + 1e-5f);
        const float m1 = s1 * (1.0f / OUTD);
        const float v1 = ss1 * (1.0f / OUTD) - m1 * m1;
        const float i1 = rsqrtf(v1 + 1e-5f);

        const bool st0 = (er0i < E), st1 = (er1i < E);
        float* o0 = out + (size_t)er0i * OUTD + 4 * qcol;
        float* o1 = out + (size_t)er1i * OUTD + 4 * qcol;
        #pragma unroll
        for (int t = 0; t < 8; t++) {   // cols 16t + 4qcol + {0..3}  (j = 2t, 2t+1)
            float4 ga = *(const float4*)(sGA + 16 * t + 4 * qcol);
            float4 be = *(const float4*)(sBE + 16 * t + 4 * qcol);
            if (st0) {
                float4 w;
                w.x = (acc2[2*t][0]   - m0) * i0 * ga.x + be.x;
                w.y = (acc2[2*t][1]   - m0) * i0 * ga.y + be.y;
                w.z = (acc2[2*t+1][0] - m0) * i0 * ga.z + be.z;
                w.w = (acc2[2*t+1][1] - m0) * i0 * ga.w + be.w;
                *(float4*)(o0 + 16 * t) = w;
            }
            if (st1) {
                float4 w;
                w.x = (acc2[2*t][2]   - m1) * i1 * ga.x + be.x;
                w.y = (acc2[2*t][3]   - m1) * i1 * ga.y + be.y;
                w.z = (acc2[2*t+1][2] - m1) * i1 * ga.z + be.z;
                w.w = (acc2[2*t+1][3] - m1) * i1 * ga.w + be.w;
                *(float4*)(o1 + 16 * t) = w;
            }
        }

        tile = ntile;
        si0 = nsi0; di0 = ndi0; si1 = nsi1; di1 = ndi1;
    }
}

// ---------------------------------------------------------------------------
extern "C" void kernel_launch(void* const* d_in, const int* in_sizes, int n_in,
                              void* d_out, int out_size)
{
    const float* efeat    = (const float*)d_in[0];
    const float* src_feat = (const float*)d_in[1];
    const float* dst_feat = (const float*)d_in[2];
    const int*   src_idx  = (const int*)d_in[3];
    const int*   dst_idx  = (const int*)d_in[4];
    const float* W_efeat  = (const float*)d_in[5];
    const float* W_src    = (const float*)d_in[6];
    const float* W_dst    = (const float*)d_in[7];
    const float* b1       = (const float*)d_in[8];
    const float* W_out    = (const float*)d_in[9];
    const float* b_out    = (const float*)d_in[10];
    const float* ln_gamma = (const float*)d_in[11];
    const float* ln_beta  = (const float*)d_in[12];
    float* out = (float*)d_out;

    const int E  = in_sizes[0] / IN_DIM;
    const int Nn = in_sizes[1] / IN_DIM;
    const int ntiles  = (E + ETILE - 1) / ETILE;
    const int ntilesN = (Nn + NROWS_N - 1) / NROWS_N;

    cudaFuncSetAttribute(node_mma_kernel, cudaFuncAttributeMaxDynamicSharedMemorySize, SMEM_NODE_BYTES);
    cudaFuncSetAttribute(edge_f16_kernel, cudaFuncAttributeMaxDynamicSharedMemorySize, SMEM_EDGE_BYTES);

    int nsm = 148;
    cudaDeviceGetAttribute(&nsm, cudaDevAttrMultiProcessorCount, 0);

    int gridN = 2 * ntilesN < nsm ? 2 * ntilesN : nsm;
    node_mma_kernel<<<gridN, NTHR, SMEM_NODE_BYTES>>>(src_feat, dst_feat, W_src, W_dst, b1, Nn, ntilesN);

    int grid = (ntiles < nsm) ? ntiles : nsm;
    edge_f16_kernel<<<grid, NTHR, SMEM_EDGE_BYTES>>>(efeat, src_idx, dst_idx, W_efeat, W_out,
                                                     b_out, ln_gamma, ln_beta, out, E, ntiles);
}